// round 12
// baseline (speedup 1.0000x reference)
#include <cuda_runtime.h>
#include <math.h>

#define Ecnt 40000
#define Bsz 32
#define Hd 128
#define NRELc 400
#define RSIZEc 200
#define TAU1 10.0f

// ---------------- scratch (static device memory; no allocs) ----------------
// state 0 is virtual (one-hot from input_x); states 1..3 are materialized.
__device__ float g_states[4][Ecnt * Bsz];   // [t][e*32+b]; index 0 unused
__device__ float g_inp[Ecnt * Bsz];         // att-combined input to propagate
__device__ unsigned char g_nz[Ecnt];        // per-entity nonzero flag for g_inp
__device__ float g_rnnT[4][Hd * Bsz];       // LSTM hidden, transposed [t][d*32+b]
__device__ float g_eatt[4][4][Bsz];         // softmaxed attention [t][tp][b]
__device__ float g_wT[3][NRELc * Bsz];      // UNNORMALIZED exp weights [t][r*32+b]
__device__ float g_sums[3][Bsz];            // per-prop-step message sums

__device__ __forceinline__ float sigf(float x) { return 1.0f / (1.0f + expf(-x)); }

__device__ __forceinline__ void red_add_v4(float4* p, float4 v) {
    asm volatile("red.global.add.v4.f32 [%0], {%1, %2, %3, %4};"
                 :: "l"(p), "f"(v.x), "f"(v.y), "f"(v.z), "f"(v.w)
                 : "memory");
}

// ===== fused: LSTM (blocks 0..31) + state/sums zeroing (blocks 32..351) ====
// LSTM reads W_ih/W_hh row-major directly (no transpose needed: same 64
// 128B-lines per warp per step, full line utilization, 16 indep LDG.128/thr).
__global__ void __launch_bounds__(1024, 1)
k_fused1(const float* __restrict__ emb_W, const int* __restrict__ input_r,
         const float* __restrict__ W_ih, const float* __restrict__ W_hh,
         const float* __restrict__ b_ih, const float* __restrict__ b_hh) {
    if (blockIdx.x >= 32) {
        // zeroing path: states 1..3 (contiguous) + sums
        int z = blockIdx.x - 32;
        int base = z * 1024 + threadIdx.x;
        const float4 zz = make_float4(0.0f, 0.0f, 0.0f, 0.0f);
        float4* s4 = reinterpret_cast<float4*>(g_states[1]);
        for (int j = base; j < 3 * Ecnt * 8; j += 320 * 1024) s4[j] = zz;
        if (z == 0 && threadIdx.x < 3 * Bsz) ((float*)g_sums)[threadIdx.x] = 0.0f;
        return;
    }
    __shared__ float xs0[Hd];
    __shared__ float xs1[Hd];
    __shared__ float cs[Hd];
    __shared__ float hist[4][Hd];
    __shared__ float gp[2][4 * Hd];
    __shared__ float attlg[4][4];
    int b = blockIdx.x, tid = threadIdx.x;
    int k = tid & 511, half = tid >> 9;
    int d0 = half * 64;
    if (tid < Hd) {
        xs0[tid] = emb_W[input_r[b] * Hd + tid];
        cs[tid] = 0.0f;
    } else if (tid < 2 * Hd) {
        xs1[tid - Hd] = emb_W[NRELc * Hd + (tid - Hd)];
    }
    __syncthreads();
    float bias = half ? 0.0f : (b_ih[k] + b_hh[k]);
    const float4* wih = reinterpret_cast<const float4*>(W_ih + k * Hd) + half * 16;
    const float4* whh = reinterpret_cast<const float4*>(W_hh + k * Hd) + half * 16;
    float p0a = bias, p0b = 0.0f, p1a = 0.0f, p1b = 0.0f;
#pragma unroll
    for (int i = 0; i < 16; i++) {
        float4 w = wih[i];
        int d = d0 + 4 * i;
        p0a += xs0[d] * w.x + xs0[d + 1] * w.y;
        p0b += xs0[d + 2] * w.z + xs0[d + 3] * w.w;
        p1a += xs1[d] * w.x + xs1[d + 1] * w.y;
        p1b += xs1[d + 2] * w.z + xs1[d + 3] * w.w;
    }
    float pre0 = p0a + p0b, pre1 = p1a + p1b + bias - bias;  // pre1 lacks bias: add below
    pre1 = p1a + p1b + bias;
    // ---- t = 0: h = 0, gates = pre0 directly
    gp[half][k] = pre0;
    __syncthreads();
    if (tid < Hd) {
        float ig = gp[0][tid] + gp[1][tid];
        float gg = gp[0][2 * Hd + tid] + gp[1][2 * Hd + tid];
        float og = gp[0][3 * Hd + tid] + gp[1][3 * Hd + tid];
        float c = sigf(ig) * tanhf(gg);   // c_prev = 0: forget term vanishes
        float h = sigf(og) * tanhf(c);
        cs[tid] = c;
        hist[0][tid] = h;
        g_rnnT[0][tid * Bsz + b] = h;
    }
    __syncthreads();
    // ---- t = 1..3
#pragma unroll
    for (int t = 1; t < 4; t++) {
        float aa = (t < 3) ? pre0 : pre1, ab = 0.0f;
        const float* hprev = hist[t - 1];
#pragma unroll
        for (int i = 0; i < 16; i++) {
            float4 w = whh[i];
            int d = d0 + 4 * i;
            aa += hprev[d] * w.x + hprev[d + 1] * w.y;
            ab += hprev[d + 2] * w.z + hprev[d + 3] * w.w;
        }
        gp[half][k] = aa + ab;
        __syncthreads();
        if (tid < Hd) {
            float ig = gp[0][tid] + gp[1][tid];
            float fg = gp[0][Hd + tid] + gp[1][Hd + tid];
            float gg = gp[0][2 * Hd + tid] + gp[1][2 * Hd + tid];
            float og = gp[0][3 * Hd + tid] + gp[1][3 * Hd + tid];
            float c = sigf(fg) * cs[tid] + sigf(ig) * tanhf(gg);
            float h = sigf(og) * tanhf(c);
            cs[tid] = c;
            hist[t][tid] = h;
            g_rnnT[t][tid * Bsz + b] = h;
        }
        __syncthreads();
    }
    // attention logits: warps 0..15 = (t,tp)
    int w = tid >> 5, lane = tid & 31;
    if (w < 16) {
        int t = w >> 2, tp = w & 3;
        if (tp <= t) {
            float acc = 0.0f;
#pragma unroll
            for (int i = 0; i < 4; i++) {
                int d = lane + 32 * i;
                acc += hist[t][d] * hist[tp][d];
            }
#pragma unroll
            for (int s = 16; s > 0; s >>= 1) acc += __shfl_xor_sync(0xffffffffu, acc, s);
            if (lane == 0) attlg[t][tp] = acc;
        }
    }
    __syncthreads();
    if (tid < 4) {
        int tt = tid;
        float m = -1e30f;
        for (int j = 0; j <= tt; j++) m = fmaxf(m, attlg[tt][j]);
        float s = 0.0f, e[4];
        for (int j = 0; j <= tt; j++) { e[j] = expf(attlg[tt][j] - m); s += e[j]; }
        float inv = 1.0f / s;
        for (int j = 0; j < 4; j++)
            g_eatt[tt][j][b] = (j <= tt) ? e[j] * inv : 0.0f;
    }
}

// ------ relation weights (blocks 0..149) + seed block (150) ----------------
// w = exp(tau * (h·linW_r + b_r)), unnormalized (softmax constants cancel).
__global__ void k_wexp(const float* __restrict__ lin_W, const float* __restrict__ lin_b,
                       const int* __restrict__ input_x) {
    if (blockIdx.x == 150) {
        // seed: zero nz flags, zero 32 one-hot lines, set one-hot entries
        int i = threadIdx.x;  // 256
        int4* nz4 = reinterpret_cast<int4*>(g_nz);
        for (int j = i; j < Ecnt / 16; j += 256) nz4[j] = make_int4(0, 0, 0, 0);
        __syncthreads();
        int e = input_x[i >> 3];
        reinterpret_cast<float4*>(g_inp)[e * 8 + (i & 7)] =
            make_float4(0.0f, 0.0f, 0.0f, 0.0f);
        __syncthreads();
        if (i < Bsz) {
            int e2 = input_x[i];
            g_inp[e2 * Bsz + i] = 1.0f;
            g_nz[e2] = 1;
        }
        return;
    }
    __shared__ float hs[Hd * Bsz];   // [d][b], 16 KB
    __shared__ float ws[8][Hd];      // 8 weight rows, 4 KB
    __shared__ float wb[8];
    int t = blockIdx.x / 50;
    int rbase = (blockIdx.x % 50) * 8;
    int tid = threadIdx.x;  // 256
    {
        const float4* src = reinterpret_cast<const float4*>(g_rnnT[t]);
        float4* dst = reinterpret_cast<float4*>(hs);
#pragma unroll
        for (int i = 0; i < 4; i++) dst[tid + 256 * i] = src[tid + 256 * i];
        const float4* wsrc = reinterpret_cast<const float4*>(lin_W + rbase * Hd);
        reinterpret_cast<float4*>(ws)[tid] = wsrc[tid];
        if (tid < 8) wb[tid] = lin_b[rbase + tid];
    }
    __syncthreads();
    int w = tid >> 5, lane = tid & 31;
    const float* wr = ws[w];
    float a0 = 0.0f, a1 = 0.0f, a2 = 0.0f, a3 = 0.0f;
#pragma unroll
    for (int d = 0; d < Hd; d += 4) {
        a0 += wr[d + 0] * hs[(d + 0) * Bsz + lane];
        a1 += wr[d + 1] * hs[(d + 1) * Bsz + lane];
        a2 += wr[d + 2] * hs[(d + 2) * Bsz + lane];
        a3 += wr[d + 3] * hs[(d + 3) * Bsz + lane];
    }
    float l = ((a0 + a1) + (a2 + a3) + wb[w]) * TAU1;
    g_wT[t][(rbase + w) * Bsz + lane] = expf(l);
}

// norm for state j (j>=1) = 1/max(g_sums[j-1][b], 1e-7); state 0 norm = 1
__device__ __forceinline__ float4 attn_vec(int t, int j, int q) {
    float4 e = reinterpret_cast<const float4*>(g_eatt)[(t * 4 + j) * 8 + q];
    if (j >= 1) {
        float4 s = reinterpret_cast<const float4*>(g_sums)[(j - 1) * 8 + q];
        e.x *= 1.0f / fmaxf(s.x, 1e-7f);
        e.y *= 1.0f / fmaxf(s.y, 1e-7f);
        e.z *= 1.0f / fmaxf(s.z, 1e-7f);
        e.w *= 1.0f / fmaxf(s.w, 1e-7f);
    }
    return e;
}

// ---------------- combine states -> g_inp + nz flags (t = 1 or 2) ----------
__global__ void k_inp(const int* __restrict__ input_x, int t) {
    int u = blockIdx.x * blockDim.x + threadIdx.x;
    int q = u & 7;
    float4 a0 = attn_vec(t, 0, q);
    float4 a1 = attn_vec(t, 1, q);
    float4 a2 = (t >= 2) ? attn_vec(t, 2, q) : make_float4(0, 0, 0, 0);
    int4 xi = reinterpret_cast<const int4*>(input_x)[q];
    const float4* __restrict__ s1 = reinterpret_cast<const float4*>(g_states[1]);
    const float4* __restrict__ s2 = reinterpret_cast<const float4*>(g_states[2]);
    int e = u >> 3;
    float4 v = make_float4(xi.x == e ? a0.x : 0.0f, xi.y == e ? a0.y : 0.0f,
                           xi.z == e ? a0.z : 0.0f, xi.w == e ? a0.w : 0.0f);
    {
        float4 s = s1[u];
        v.x += a1.x * s.x; v.y += a1.y * s.y; v.z += a1.z * s.z; v.w += a1.w * s.w;
    }
    if (t >= 2) {
        float4 s = s2[u];
        v.x += a2.x * s.x; v.y += a2.y * s.y; v.z += a2.z * s.z; v.w += a2.w * s.w;
    }
    reinterpret_cast<float4*>(g_inp)[u] = v;
    int lane = threadIdx.x & 31;
    bool nzv = (v.x != 0.0f) | (v.y != 0.0f) | (v.z != 0.0f) | (v.w != 0.0f);
    unsigned m = __ballot_sync(0xffffffffu, nzv);
    if ((lane & 7) == 0) g_nz[e] = ((m >> ((lane >> 3) * 8)) & 0xffu) ? 1 : 0;
}

// ---------------- propagate: sparse-aware, fused batch sums ----------------
__global__ void k_prop(const int* __restrict__ heads, const int* __restrict__ tails,
                       const int* __restrict__ rels, int t, int nE) {
    const float4* __restrict__ x4 = reinterpret_cast<const float4*>(g_inp);
    float4* s4 = reinterpret_cast<float4*>(g_states[t + 1]);
    const float4* __restrict__ w4 = reinterpret_cast<const float4*>(g_wT[t]);
    int lane = threadIdx.x & 31;
    int q = lane & 7;
    int sub = lane >> 3;
    int warpId = (blockIdx.x * blockDim.x + threadIdx.x) >> 5;
    int nWarp = (gridDim.x * blockDim.x) >> 5;
    float4 acc = make_float4(0.0f, 0.0f, 0.0f, 0.0f);
    for (int e = warpId * 4 + sub; e < nE; e += nWarp * 4) {
        int h = heads[e], tl = tails[e];
        bool fh = g_nz[h] != 0, ft = g_nz[tl] != 0;
        if (fh | ft) {
            int r = rels[e];
            if (fh) {
                float4 xh = x4[h * 8 + q];
                if (xh.x != 0.0f || xh.y != 0.0f || xh.z != 0.0f || xh.w != 0.0f) {
                    float4 w1 = w4[r * 8 + q];
                    float4 m1 = make_float4(xh.x * w1.x, xh.y * w1.y,
                                            xh.z * w1.z, xh.w * w1.w);
                    red_add_v4(&s4[tl * 8 + q], m1);
                    acc.x += m1.x; acc.y += m1.y; acc.z += m1.z; acc.w += m1.w;
                }
            }
            if (ft) {
                float4 xt = x4[tl * 8 + q];
                if (xt.x != 0.0f || xt.y != 0.0f || xt.z != 0.0f || xt.w != 0.0f) {
                    float4 w2 = w4[(r + RSIZEc) * 8 + q];
                    float4 m2 = make_float4(xt.x * w2.x, xt.y * w2.y,
                                            xt.z * w2.z, xt.w * w2.w);
                    red_add_v4(&s4[h * 8 + q], m2);
                    acc.x += m2.x; acc.y += m2.y; acc.z += m2.z; acc.w += m2.w;
                }
            }
        }
    }
    acc.x += __shfl_xor_sync(0xffffffffu, acc.x, 8);
    acc.y += __shfl_xor_sync(0xffffffffu, acc.y, 8);
    acc.z += __shfl_xor_sync(0xffffffffu, acc.z, 8);
    acc.w += __shfl_xor_sync(0xffffffffu, acc.w, 8);
    acc.x += __shfl_xor_sync(0xffffffffu, acc.x, 16);
    acc.y += __shfl_xor_sync(0xffffffffu, acc.y, 16);
    acc.z += __shfl_xor_sync(0xffffffffu, acc.z, 16);
    acc.w += __shfl_xor_sync(0xffffffffu, acc.w, 16);
    __shared__ float sblk[Bsz];
    if (threadIdx.x < Bsz) sblk[threadIdx.x] = 0.0f;
    __syncthreads();
    if (lane < 8) {
        atomicAdd(&sblk[q * 4 + 0], acc.x);
        atomicAdd(&sblk[q * 4 + 1], acc.y);
        atomicAdd(&sblk[q * 4 + 2], acc.z);
        atomicAdd(&sblk[q * 4 + 3], acc.w);
    }
    __syncthreads();
    if (threadIdx.x < Bsz) atomicAdd(&g_sums[t][threadIdx.x], sblk[threadIdx.x]);
}

// ---------------- final combine, tiled transpose to (B, E) ------------------
__global__ void k_final(const int* __restrict__ input_x, float* __restrict__ out) {
    __shared__ float tile[32][33];
    int e0 = blockIdx.x * 32;
    int r = threadIdx.x >> 3, q = threadIdx.x & 7;
    float4 a0 = attn_vec(3, 0, q);
    float4 a1 = attn_vec(3, 1, q);
    float4 a2 = attn_vec(3, 2, q);
    float4 a3 = attn_vec(3, 3, q);
    int4 xi = reinterpret_cast<const int4*>(input_x)[q];
    const float4* __restrict__ s1 = reinterpret_cast<const float4*>(g_states[1]);
    const float4* __restrict__ s2 = reinterpret_cast<const float4*>(g_states[2]);
    const float4* __restrict__ s3 = reinterpret_cast<const float4*>(g_states[3]);
    int e = e0 + r;
    int u = e * 8 + q;
    float4 v1 = s1[u], v2 = s2[u], v3 = s3[u];
    float4 v;
    v.x = (xi.x == e ? a0.x : 0.0f) + a1.x * v1.x + a2.x * v2.x + a3.x * v3.x;
    v.y = (xi.y == e ? a0.y : 0.0f) + a1.y * v1.y + a2.y * v2.y + a3.y * v3.y;
    v.z = (xi.z == e ? a0.z : 0.0f) + a1.z * v1.z + a2.z * v2.z + a3.z * v3.z;
    v.w = (xi.w == e ? a0.w : 0.0f) + a1.w * v1.w + a2.w * v2.w + a3.w * v3.w;
    tile[r][4 * q + 0] = v.x;
    tile[r][4 * q + 1] = v.y;
    tile[r][4 * q + 2] = v.z;
    tile[r][4 * q + 3] = v.w;
    __syncthreads();
    int w = threadIdx.x >> 5, lane = threadIdx.x & 31;
#pragma unroll
    for (int bb = 0; bb < 4; bb++) {
        int b = w * 4 + bb;
        out[b * Ecnt + e0 + lane] = tile[lane][b];
    }
}

// ---------------- launch ----------------------------------------------------
extern "C" void kernel_launch(void* const* d_in, const int* in_sizes, int n_in,
                              void* d_out, int out_size) {
    const int* input_x = (const int*)d_in[0];
    const int* input_r = (const int*)d_in[1];
    const int* heads   = (const int*)d_in[2];
    const int* tails   = (const int*)d_in[3];
    const int* rels    = (const int*)d_in[4];
    const float* emb_W = (const float*)d_in[5];
    const float* W_ih  = (const float*)d_in[6];
    const float* W_hh  = (const float*)d_in[7];
    const float* b_ih  = (const float*)d_in[8];
    const float* b_hh  = (const float*)d_in[9];
    const float* lin_W = (const float*)d_in[10];
    const float* lin_b = (const float*)d_in[11];
    int nE = in_sizes[2];
    float* out = (float*)d_out;

    k_fused1<<<352, 1024>>>(emb_W, input_r, W_ih, W_hh, b_ih, b_hh);
    k_wexp<<<151, 256>>>(lin_W, lin_b, input_x);
    k_prop<<<1184, 256>>>(heads, tails, rels, 0, nE);
    for (int t = 1; t < 3; t++) {
        k_inp<<<1250, 256>>>(input_x, t);
        k_prop<<<1184, 256>>>(heads, tails, rels, t, nE);
    }
    k_final<<<1250, 256>>>(input_x, out);
}

// round 13
// speedup vs baseline: 1.0861x; 1.0861x over previous
#include <cuda_runtime.h>
#include <math.h>

#define Ecnt 40000
#define Bsz 32
#define Hd 128
#define NRELc 400
#define RSIZEc 200
#define TAU1 10.0f

// ---------------- scratch (static device memory; no allocs) ----------------
// state 0 is virtual (one-hot from input_x); states 1..3 are materialized.
__device__ float g_states[4][Ecnt * Bsz];   // [t][e*32+b]; index 0 unused
__device__ float g_inp[Ecnt * Bsz];         // att-combined input to propagate
__device__ unsigned char g_nz[Ecnt];        // per-entity nonzero flag for g_inp
__device__ float g_rnnT[4][Hd * Bsz];       // LSTM hidden, transposed [t][d*32+b]
__device__ float g_eatt[4][4][Bsz];         // softmaxed attention [t][tp][b]
__device__ float g_WihT[Hd * 4 * Hd];       // [d][k]
__device__ float g_WhhT[Hd * 4 * Hd];       // [d][k]
__device__ float g_wT[3][NRELc * Bsz];      // UNNORMALIZED exp weights [t][r*32+b]
__device__ float g_sums[3][Bsz];            // per-prop-step message sums

__device__ __forceinline__ float sigf(float x) { return 1.0f / (1.0f + expf(-x)); }

__device__ __forceinline__ void red_add_v4(float4* p, float4 v) {
    asm volatile("red.global.add.v4.f32 [%0], {%1, %2, %3, %4};"
                 :: "l"(p), "f"(v.x), "f"(v.y), "f"(v.z), "f"(v.w)
                 : "memory");
}

// ---------------- pre: zero state[1] + nz + sums (slim) ----------------
__global__ void k_pre() {
    int i = blockIdx.x * blockDim.x + threadIdx.x;   // 320*256 = 81920
    const float4 z = make_float4(0.0f, 0.0f, 0.0f, 0.0f);
    float4* s4 = reinterpret_cast<float4*>(g_states[1]);
    for (int j = i; j < Ecnt * 8; j += 81920) s4[j] = z;
    if (i < Ecnt / 16) reinterpret_cast<int4*>(g_nz)[i] = make_int4(0, 0, 0, 0);
    if (i < 3 * Bsz) ((float*)g_sums)[i] = 0.0f;
}

// ------ tiled transposes of W_ih / W_hh + (block 128) seed of t=0 input ----
__global__ void k_trans(const float* __restrict__ W_ih,
                        const float* __restrict__ W_hh,
                        const int* __restrict__ input_x) {
    if (blockIdx.x == 128) {
        // seed: zero the 32 one-hot lines, then set the one-hot entries
        int i = threadIdx.x;  // 256 threads
        int e = input_x[i >> 3];
        reinterpret_cast<float4*>(g_inp)[e * 8 + (i & 7)] =
            make_float4(0.0f, 0.0f, 0.0f, 0.0f);
        __syncthreads();
        if (i < Bsz) {
            int e2 = input_x[i];
            g_inp[e2 * Bsz + i] = 1.0f;
            g_nz[e2] = 1;
        }
        return;
    }
    __shared__ float tile[32][33];
    int m = blockIdx.x >> 6;           // 0: ih, 1: hh
    int bid = blockIdx.x & 63;
    int kb = (bid >> 2) * 32;
    int db = (bid & 3) * 32;
    const float* __restrict__ W = m ? W_hh : W_ih;
    float* WT = m ? g_WhhT : g_WihT;
    int tx = threadIdx.x & 31, ty0 = threadIdx.x >> 5;   // 32x8
#pragma unroll
    for (int i = 0; i < 4; i++) {
        int ty = ty0 + 8 * i;
        tile[ty][tx] = W[(kb + ty) * Hd + db + tx];
    }
    __syncthreads();
#pragma unroll
    for (int i = 0; i < 4; i++) {
        int ty = ty0 + 8 * i;
        WT[(db + ty) * (4 * Hd) + kb + tx] = tile[tx][ty];
    }
}

// ------- LSTM: ih-pre + 4 steps + attention, d-split x2, 1024 thr ----------
__global__ void __launch_bounds__(1024, 1)
k_lstm4(const float* __restrict__ emb_W, const int* __restrict__ input_r,
        const float* __restrict__ b_ih, const float* __restrict__ b_hh) {
    __shared__ float xs0[Hd];
    __shared__ float xs1[Hd];
    __shared__ float cs[Hd];
    __shared__ float hist[4][Hd];
    __shared__ float gp[2][4 * Hd];
    __shared__ float attlg[4][4];
    int b = blockIdx.x, tid = threadIdx.x;
    int k = tid & 511, half = tid >> 9;
    int d0 = half * 64;
    if (tid < Hd) {
        xs0[tid] = emb_W[input_r[b] * Hd + tid];
        cs[tid] = 0.0f;
    } else if (tid < 2 * Hd) {
        xs1[tid - Hd] = emb_W[NRELc * Hd + (tid - Hd)];
    }
    __syncthreads();
    float bias = half ? 0.0f : (b_ih[k] + b_hh[k]);
    float p0a = bias, p0b = 0.0f, p1a = bias, p1b = 0.0f;
#pragma unroll 8
    for (int i = 0; i < 64; i += 2) {
        int d = d0 + i;
        float wa = g_WihT[d * (4 * Hd) + k];
        float wb = g_WihT[(d + 1) * (4 * Hd) + k];
        p0a += xs0[d] * wa;     p0b += xs0[d + 1] * wb;
        p1a += xs1[d] * wa;     p1b += xs1[d + 1] * wb;
    }
    float pre0 = p0a + p0b, pre1 = p1a + p1b;
    // ---- t = 0: h = 0, gates = pre0 directly
    gp[half][k] = pre0;
    __syncthreads();
    if (tid < Hd) {
        float ig = gp[0][tid] + gp[1][tid];
        float gg = gp[0][2 * Hd + tid] + gp[1][2 * Hd + tid];
        float og = gp[0][3 * Hd + tid] + gp[1][3 * Hd + tid];
        float c = sigf(ig) * tanhf(gg);   // c_prev = 0: forget term vanishes
        float h = sigf(og) * tanhf(c);
        cs[tid] = c;
        hist[0][tid] = h;
        g_rnnT[0][tid * Bsz + b] = h;
    }
    __syncthreads();
    // ---- t = 1..3
#pragma unroll
    for (int t = 1; t < 4; t++) {
        float aa = (t < 3) ? pre0 : pre1, ab = 0.0f;
        const float* hprev = hist[t - 1];
#pragma unroll 8
        for (int i = 0; i < 64; i += 2) {
            int d = d0 + i;
            aa += hprev[d] * g_WhhT[d * (4 * Hd) + k];
            ab += hprev[d + 1] * g_WhhT[(d + 1) * (4 * Hd) + k];
        }
        gp[half][k] = aa + ab;
        __syncthreads();
        if (tid < Hd) {
            float ig = gp[0][tid] + gp[1][tid];
            float fg = gp[0][Hd + tid] + gp[1][Hd + tid];
            float gg = gp[0][2 * Hd + tid] + gp[1][2 * Hd + tid];
            float og = gp[0][3 * Hd + tid] + gp[1][3 * Hd + tid];
            float c = sigf(fg) * cs[tid] + sigf(ig) * tanhf(gg);
            float h = sigf(og) * tanhf(c);
            cs[tid] = c;
            hist[t][tid] = h;
            g_rnnT[t][tid * Bsz + b] = h;
        }
        __syncthreads();
    }
    // attention logits: warps 0..15 = (t,tp)
    int w = tid >> 5, lane = tid & 31;
    if (w < 16) {
        int t = w >> 2, tp = w & 3;
        if (tp <= t) {
            float acc = 0.0f;
#pragma unroll
            for (int i = 0; i < 4; i++) {
                int d = lane + 32 * i;
                acc += hist[t][d] * hist[tp][d];
            }
#pragma unroll
            for (int s = 16; s > 0; s >>= 1) acc += __shfl_xor_sync(0xffffffffu, acc, s);
            if (lane == 0) attlg[t][tp] = acc;
        }
    }
    __syncthreads();
    if (tid < 4) {
        int tt = tid;
        float m = -1e30f;
        for (int j = 0; j <= tt; j++) m = fmaxf(m, attlg[tt][j]);
        float s = 0.0f, e[4];
        for (int j = 0; j <= tt; j++) { e[j] = expf(attlg[tt][j] - m); s += e[j]; }
        float inv = 1.0f / s;
        for (int j = 0; j < 4; j++)
            g_eatt[tt][j][b] = (j <= tt) ? e[j] * inv : 0.0f;
    }
}

// ------ relation weights, UNNORMALIZED: w = exp(tau * (h·linW_r + b_r)) -----
// smem-staged, warp-pair split: 512 thr, warps (2r, 2r+1) split d-range of
// relation r; partials combined in smem. Halves the serial LDS chain.
__global__ void k_wexp(const float* __restrict__ lin_W, const float* __restrict__ lin_b) {
    __shared__ float hs[Hd * Bsz];   // [d][b], 16 KB
    __shared__ float ws[8][Hd];      // 8 weight rows, 4 KB
    __shared__ float wb[8];
    __shared__ float part[8][2][Bsz];
    int t = blockIdx.x / 50;
    int rbase = (blockIdx.x % 50) * 8;
    int tid = threadIdx.x;  // 512
    {
        const float4* src = reinterpret_cast<const float4*>(g_rnnT[t]);
        float4* dst = reinterpret_cast<float4*>(hs);
#pragma unroll
        for (int i = 0; i < 2; i++) dst[tid + 512 * i] = src[tid + 512 * i];
        if (tid < 256) {
            const float4* wsrc = reinterpret_cast<const float4*>(lin_W + rbase * Hd);
            reinterpret_cast<float4*>(ws)[tid] = wsrc[tid];
        }
        if (tid < 8) wb[tid] = lin_b[rbase + tid];
    }
    __syncthreads();
    int w = tid >> 5, lane = tid & 31;
    int rl = w >> 1, p = w & 1;
    const float* wr = ws[rl] + 64 * p;
    const float* hb = hs + 64 * p * Bsz;
    float a0 = 0.0f, a1 = 0.0f, a2 = 0.0f, a3 = 0.0f;
#pragma unroll
    for (int d = 0; d < 64; d += 4) {
        a0 += wr[d + 0] * hb[(d + 0) * Bsz + lane];
        a1 += wr[d + 1] * hb[(d + 1) * Bsz + lane];
        a2 += wr[d + 2] * hb[(d + 2) * Bsz + lane];
        a3 += wr[d + 3] * hb[(d + 3) * Bsz + lane];
    }
    part[rl][p][lane] = (a0 + a1) + (a2 + a3);
    __syncthreads();
    if (tid < 256) {
        int r = tid >> 5, b = tid & 31;
        float l = (part[r][0][b] + part[r][1][b] + wb[r]) * TAU1;
        g_wT[t][(rbase + r) * Bsz + b] = expf(l);
    }
}

// norm for state j (j>=1) = 1/max(g_sums[j-1][b], 1e-7); state 0 norm = 1
__device__ __forceinline__ float4 attn_vec(int t, int j, int q) {
    float4 e = reinterpret_cast<const float4*>(g_eatt)[(t * 4 + j) * 8 + q];
    if (j >= 1) {
        float4 s = reinterpret_cast<const float4*>(g_sums)[(j - 1) * 8 + q];
        e.x *= 1.0f / fmaxf(s.x, 1e-7f);
        e.y *= 1.0f / fmaxf(s.y, 1e-7f);
        e.z *= 1.0f / fmaxf(s.z, 1e-7f);
        e.w *= 1.0f / fmaxf(s.w, 1e-7f);
    }
    return e;
}

// ------- combine states -> g_inp + nz flags + zero next state (t=1,2) ------
// grid-stride x4: amortizes the attn/sums prologue loads.
__global__ void k_inp(const int* __restrict__ input_x, int t) {
    int tid0 = blockIdx.x * blockDim.x + threadIdx.x;   // 320*256 = 81920
    int q = tid0 & 7;                                    // stride 81920 % 8 == 0
    float4 a0 = attn_vec(t, 0, q);
    float4 a1 = attn_vec(t, 1, q);
    float4 a2 = (t >= 2) ? attn_vec(t, 2, q) : make_float4(0, 0, 0, 0);
    int4 xi = reinterpret_cast<const int4*>(input_x)[q];
    const float4* __restrict__ s1 = reinterpret_cast<const float4*>(g_states[1]);
    const float4* __restrict__ s2 = reinterpret_cast<const float4*>(g_states[2]);
    float4* inp4 = reinterpret_cast<float4*>(g_inp);
    float4* snew = reinterpret_cast<float4*>(g_states[t + 1]);
    const float4 z = make_float4(0.0f, 0.0f, 0.0f, 0.0f);
    int lane = threadIdx.x & 31;
    for (int u = tid0; u < Ecnt * 8; u += 81920) {
        int e = u >> 3;
        float4 v = make_float4(xi.x == e ? a0.x : 0.0f, xi.y == e ? a0.y : 0.0f,
                               xi.z == e ? a0.z : 0.0f, xi.w == e ? a0.w : 0.0f);
        {
            float4 s = s1[u];
            v.x += a1.x * s.x; v.y += a1.y * s.y; v.z += a1.z * s.z; v.w += a1.w * s.w;
        }
        if (t >= 2) {
            float4 s = s2[u];
            v.x += a2.x * s.x; v.y += a2.y * s.y; v.z += a2.z * s.z; v.w += a2.w * s.w;
        }
        inp4[u] = v;
        snew[u] = z;
        bool nzv = (v.x != 0.0f) | (v.y != 0.0f) | (v.z != 0.0f) | (v.w != 0.0f);
        unsigned m = __ballot_sync(0xffffffffu, nzv);
        if ((lane & 7) == 0) g_nz[e] = ((m >> ((lane >> 3) * 8)) & 0xffu) ? 1 : 0;
    }
}

// ---------------- propagate: sparse-aware, fused batch sums ----------------
__global__ void k_prop(const int* __restrict__ heads, const int* __restrict__ tails,
                       const int* __restrict__ rels, int t, int nE) {
    const float4* __restrict__ x4 = reinterpret_cast<const float4*>(g_inp);
    float4* s4 = reinterpret_cast<float4*>(g_states[t + 1]);
    const float4* __restrict__ w4 = reinterpret_cast<const float4*>(g_wT[t]);
    int lane = threadIdx.x & 31;
    int q = lane & 7;
    int sub = lane >> 3;
    int warpId = (blockIdx.x * blockDim.x + threadIdx.x) >> 5;
    int nWarp = (gridDim.x * blockDim.x) >> 5;
    float4 acc = make_float4(0.0f, 0.0f, 0.0f, 0.0f);
    for (int e = warpId * 4 + sub; e < nE; e += nWarp * 4) {
        int h = heads[e], tl = tails[e];
        bool fh = g_nz[h] != 0, ft = g_nz[tl] != 0;
        if (fh | ft) {
            int r = rels[e];
            if (fh) {
                float4 xh = x4[h * 8 + q];
                if (xh.x != 0.0f || xh.y != 0.0f || xh.z != 0.0f || xh.w != 0.0f) {
                    float4 w1 = w4[r * 8 + q];
                    float4 m1 = make_float4(xh.x * w1.x, xh.y * w1.y,
                                            xh.z * w1.z, xh.w * w1.w);
                    red_add_v4(&s4[tl * 8 + q], m1);
                    acc.x += m1.x; acc.y += m1.y; acc.z += m1.z; acc.w += m1.w;
                }
            }
            if (ft) {
                float4 xt = x4[tl * 8 + q];
                if (xt.x != 0.0f || xt.y != 0.0f || xt.z != 0.0f || xt.w != 0.0f) {
                    float4 w2 = w4[(r + RSIZEc) * 8 + q];
                    float4 m2 = make_float4(xt.x * w2.x, xt.y * w2.y,
                                            xt.z * w2.z, xt.w * w2.w);
                    red_add_v4(&s4[h * 8 + q], m2);
                    acc.x += m2.x; acc.y += m2.y; acc.z += m2.z; acc.w += m2.w;
                }
            }
        }
    }
    acc.x += __shfl_xor_sync(0xffffffffu, acc.x, 8);
    acc.y += __shfl_xor_sync(0xffffffffu, acc.y, 8);
    acc.z += __shfl_xor_sync(0xffffffffu, acc.z, 8);
    acc.w += __shfl_xor_sync(0xffffffffu, acc.w, 8);
    acc.x += __shfl_xor_sync(0xffffffffu, acc.x, 16);
    acc.y += __shfl_xor_sync(0xffffffffu, acc.y, 16);
    acc.z += __shfl_xor_sync(0xffffffffu, acc.z, 16);
    acc.w += __shfl_xor_sync(0xffffffffu, acc.w, 16);
    __shared__ float sblk[Bsz];
    if (threadIdx.x < Bsz) sblk[threadIdx.x] = 0.0f;
    __syncthreads();
    if (lane < 8) {
        atomicAdd(&sblk[q * 4 + 0], acc.x);
        atomicAdd(&sblk[q * 4 + 1], acc.y);
        atomicAdd(&sblk[q * 4 + 2], acc.z);
        atomicAdd(&sblk[q * 4 + 3], acc.w);
    }
    __syncthreads();
    if (threadIdx.x < Bsz) atomicAdd(&g_sums[t][threadIdx.x], sblk[threadIdx.x]);
}

// ------- final combine, tiled transpose to (B, E); 2 tiles per block -------
__global__ void k_final(const int* __restrict__ input_x, float* __restrict__ out) {
    __shared__ float tile[32][33];
    int r = threadIdx.x >> 3, q = threadIdx.x & 7;
    float4 a0 = attn_vec(3, 0, q);
    float4 a1 = attn_vec(3, 1, q);
    float4 a2 = attn_vec(3, 2, q);
    float4 a3 = attn_vec(3, 3, q);
    int4 xi = reinterpret_cast<const int4*>(input_x)[q];
    const float4* __restrict__ s1 = reinterpret_cast<const float4*>(g_states[1]);
    const float4* __restrict__ s2 = reinterpret_cast<const float4*>(g_states[2]);
    const float4* __restrict__ s3 = reinterpret_cast<const float4*>(g_states[3]);
    int w = threadIdx.x >> 5, lane = threadIdx.x & 31;
#pragma unroll
    for (int tt = 0; tt < 2; tt++) {
        int e0 = blockIdx.x * 64 + tt * 32;
        int e = e0 + r;
        int u = e * 8 + q;
        float4 v1 = s1[u], v2 = s2[u], v3 = s3[u];
        float4 v;
        v.x = (xi.x == e ? a0.x : 0.0f) + a1.x * v1.x + a2.x * v2.x + a3.x * v3.x;
        v.y = (xi.y == e ? a0.y : 0.0f) + a1.y * v1.y + a2.y * v2.y + a3.y * v3.y;
        v.z = (xi.z == e ? a0.z : 0.0f) + a1.z * v1.z + a2.z * v2.z + a3.z * v3.z;
        v.w = (xi.w == e ? a0.w : 0.0f) + a1.w * v1.w + a2.w * v2.w + a3.w * v3.w;
        tile[r][4 * q + 0] = v.x;
        tile[r][4 * q + 1] = v.y;
        tile[r][4 * q + 2] = v.z;
        tile[r][4 * q + 3] = v.w;
        __syncthreads();
#pragma unroll
        for (int bb = 0; bb < 4; bb++) {
            int b = w * 4 + bb;
            out[b * Ecnt + e0 + lane] = tile[lane][b];
        }
        __syncthreads();
    }
}

// ---------------- launch ----------------------------------------------------
extern "C" void kernel_launch(void* const* d_in, const int* in_sizes, int n_in,
                              void* d_out, int out_size) {
    const int* input_x = (const int*)d_in[0];
    const int* input_r = (const int*)d_in[1];
    const int* heads   = (const int*)d_in[2];
    const int* tails   = (const int*)d_in[3];
    const int* rels    = (const int*)d_in[4];
    const float* emb_W = (const float*)d_in[5];
    const float* W_ih  = (const float*)d_in[6];
    const float* W_hh  = (const float*)d_in[7];
    const float* b_ih  = (const float*)d_in[8];
    const float* b_hh  = (const float*)d_in[9];
    const float* lin_W = (const float*)d_in[10];
    const float* lin_b = (const float*)d_in[11];
    int nE = in_sizes[2];
    float* out = (float*)d_out;

    k_pre<<<320, 256>>>();
    k_trans<<<129, 256>>>(W_ih, W_hh, input_x);
    k_lstm4<<<32, 1024>>>(emb_W, input_r, b_ih, b_hh);
    k_wexp<<<150, 512>>>(lin_W, lin_b);
    k_prop<<<1184, 256>>>(heads, tails, rels, 0, nE);
    for (int t = 1; t < 3; t++) {
        k_inp<<<320, 256>>>(input_x, t);
        k_prop<<<1184, 256>>>(heads, tails, rels, t, nE);
    }
    k_final<<<625, 256>>>(input_x, out);
}

// round 14
// speedup vs baseline: 1.1055x; 1.0179x over previous
#include <cuda_runtime.h>
#include <math.h>

#define Ecnt 40000
#define Bsz 32
#define Hd 128
#define NRELc 400
#define RSIZEc 200
#define TAU1 10.0f
#define NEMAX 1000000

// ---------------- scratch (static device memory; no allocs) ----------------
// state 0 is virtual (one-hot from input_x); states 1..3 are materialized.
__device__ float g_states[4][Ecnt * Bsz];   // [t][e*32+b]; index 0 unused
__device__ float g_inp[Ecnt * Bsz];         // att-combined input to propagate
__device__ unsigned char g_nz[Ecnt];        // per-entity nonzero flag for g_inp
__device__ unsigned g_ht[NEMAX];            // packed (head<<16)|tail per edge
__device__ float g_rnnT[4][Hd * Bsz];       // LSTM hidden, transposed [t][d*32+b]
__device__ float g_eatt[4][4][Bsz];         // softmaxed attention [t][tp][b]
__device__ float g_WihT[Hd * 4 * Hd];       // [d][k]
__device__ float g_WhhT[Hd * 4 * Hd];       // [d][k]
__device__ float g_wT[3][NRELc * Bsz];      // UNNORMALIZED exp weights [t][r*32+b]
__device__ float g_sums[3][Bsz];            // per-prop-step message sums

__device__ __forceinline__ float sigf(float x) { return 1.0f / (1.0f + expf(-x)); }

__device__ __forceinline__ void red_add_v4(float4* p, float4 v) {
    asm volatile("red.global.add.v4.f32 [%0], {%1, %2, %3, %4};"
                 :: "l"(p), "f"(v.x), "f"(v.y), "f"(v.z), "f"(v.w)
                 : "memory");
}

// ===== prep: transposes (0..127) + seed (128) + edge pack (129..288) =======
// ===== + state/sums zeroing (289..448)                                 =====
__global__ void k_prep(const float* __restrict__ W_ih,
                       const float* __restrict__ W_hh,
                       const int* __restrict__ input_x,
                       const int* __restrict__ heads,
                       const int* __restrict__ tails, int nE) {
    int bx = blockIdx.x;
    if (bx < 128) {
        __shared__ float tile[32][33];
        int m = bx >> 6;           // 0: ih, 1: hh
        int bid = bx & 63;
        int kb = (bid >> 2) * 32;
        int db = (bid & 3) * 32;
        const float* __restrict__ W = m ? W_hh : W_ih;
        float* WT = m ? g_WhhT : g_WihT;
        int tx = threadIdx.x & 31, ty0 = threadIdx.x >> 5;   // 32x8
#pragma unroll
        for (int i = 0; i < 4; i++) {
            int ty = ty0 + 8 * i;
            tile[ty][tx] = W[(kb + ty) * Hd + db + tx];
        }
        __syncthreads();
#pragma unroll
        for (int i = 0; i < 4; i++) {
            int ty = ty0 + 8 * i;
            WT[(db + ty) * (4 * Hd) + kb + tx] = tile[tx][ty];
        }
    } else if (bx == 128) {
        // seed: zero nz flags, zero 32 one-hot lines, set one-hot entries
        int i = threadIdx.x;  // 256
        int4* nz4 = reinterpret_cast<int4*>(g_nz);
        for (int j = i; j < Ecnt / 16; j += 256) nz4[j] = make_int4(0, 0, 0, 0);
        __syncthreads();
        int e = input_x[i >> 3];
        reinterpret_cast<float4*>(g_inp)[e * 8 + (i & 7)] =
            make_float4(0.0f, 0.0f, 0.0f, 0.0f);
        __syncthreads();
        if (i < Bsz) {
            int e2 = input_x[i];
            g_inp[e2 * Bsz + i] = 1.0f;
            g_nz[e2] = 1;
        }
    } else if (bx < 289) {
        // pack edges: h,t < 40000 < 2^16
        int i = (bx - 129) * 256 + threadIdx.x;  // 40960 threads
        for (int e = i; e < nE; e += 160 * 256)
            g_ht[e] = ((unsigned)heads[e] << 16) | (unsigned)tails[e];
    } else {
        // zero state[1] + sums
        int i = (bx - 289) * 256 + threadIdx.x;  // 40960 threads
        const float4 z = make_float4(0.0f, 0.0f, 0.0f, 0.0f);
        float4* s4 = reinterpret_cast<float4*>(g_states[1]);
        for (int j = i; j < Ecnt * 8; j += 160 * 256) s4[j] = z;
        if (i < 3 * Bsz) ((float*)g_sums)[i] = 0.0f;
    }
}

// ------- LSTM: ih-pre + 4 steps + attention, d-split x2, 1024 thr ----------
__global__ void __launch_bounds__(1024, 1)
k_lstm4(const float* __restrict__ emb_W, const int* __restrict__ input_r,
        const float* __restrict__ b_ih, const float* __restrict__ b_hh) {
    __shared__ float xs0[Hd];
    __shared__ float xs1[Hd];
    __shared__ float cs[Hd];
    __shared__ float hist[4][Hd];
    __shared__ float gp[2][4 * Hd];
    __shared__ float attlg[4][4];
    int b = blockIdx.x, tid = threadIdx.x;
    int k = tid & 511, half = tid >> 9;
    int d0 = half * 64;
    if (tid < Hd) {
        xs0[tid] = emb_W[input_r[b] * Hd + tid];
        cs[tid] = 0.0f;
    } else if (tid < 2 * Hd) {
        xs1[tid - Hd] = emb_W[NRELc * Hd + (tid - Hd)];
    }
    __syncthreads();
    float bias = half ? 0.0f : (b_ih[k] + b_hh[k]);
    float p0a = bias, p0b = 0.0f, p1a = bias, p1b = 0.0f;
#pragma unroll
    for (int i = 0; i < 64; i += 2) {
        int d = d0 + i;
        float wa = g_WihT[d * (4 * Hd) + k];
        float wb = g_WihT[(d + 1) * (4 * Hd) + k];
        p0a += xs0[d] * wa;     p0b += xs0[d + 1] * wb;
        p1a += xs1[d] * wa;     p1b += xs1[d + 1] * wb;
    }
    float pre0 = p0a + p0b, pre1 = p1a + p1b;
    // ---- t = 0: h = 0, gates = pre0 directly
    gp[half][k] = pre0;
    __syncthreads();
    if (tid < Hd) {
        float ig = gp[0][tid] + gp[1][tid];
        float gg = gp[0][2 * Hd + tid] + gp[1][2 * Hd + tid];
        float og = gp[0][3 * Hd + tid] + gp[1][3 * Hd + tid];
        float c = sigf(ig) * tanhf(gg);   // c_prev = 0: forget term vanishes
        float h = sigf(og) * tanhf(c);
        cs[tid] = c;
        hist[0][tid] = h;
        g_rnnT[0][tid * Bsz + b] = h;
    }
    __syncthreads();
    // ---- t = 1..3: full unroll, 4 accumulators for MLP
#pragma unroll
    for (int t = 1; t < 4; t++) {
        float aa = (t < 3) ? pre0 : pre1, ab = 0.0f, ac = 0.0f, ad = 0.0f;
        const float* hprev = hist[t - 1];
#pragma unroll
        for (int i = 0; i < 64; i += 4) {
            int d = d0 + i;
            aa += hprev[d] * g_WhhT[d * (4 * Hd) + k];
            ab += hprev[d + 1] * g_WhhT[(d + 1) * (4 * Hd) + k];
            ac += hprev[d + 2] * g_WhhT[(d + 2) * (4 * Hd) + k];
            ad += hprev[d + 3] * g_WhhT[(d + 3) * (4 * Hd) + k];
        }
        gp[half][k] = (aa + ab) + (ac + ad);
        __syncthreads();
        if (tid < Hd) {
            float ig = gp[0][tid] + gp[1][tid];
            float fg = gp[0][Hd + tid] + gp[1][Hd + tid];
            float gg = gp[0][2 * Hd + tid] + gp[1][2 * Hd + tid];
            float og = gp[0][3 * Hd + tid] + gp[1][3 * Hd + tid];
            float c = sigf(fg) * cs[tid] + sigf(ig) * tanhf(gg);
            float h = sigf(og) * tanhf(c);
            cs[tid] = c;
            hist[t][tid] = h;
            g_rnnT[t][tid * Bsz + b] = h;
        }
        __syncthreads();
    }
    // attention logits: warps 0..15 = (t,tp)
    int w = tid >> 5, lane = tid & 31;
    if (w < 16) {
        int t = w >> 2, tp = w & 3;
        if (tp <= t) {
            float acc = 0.0f;
#pragma unroll
            for (int i = 0; i < 4; i++) {
                int d = lane + 32 * i;
                acc += hist[t][d] * hist[tp][d];
            }
#pragma unroll
            for (int s = 16; s > 0; s >>= 1) acc += __shfl_xor_sync(0xffffffffu, acc, s);
            if (lane == 0) attlg[t][tp] = acc;
        }
    }
    __syncthreads();
    if (tid < 4) {
        int tt = tid;
        float m = -1e30f;
        for (int j = 0; j <= tt; j++) m = fmaxf(m, attlg[tt][j]);
        float s = 0.0f, e[4];
        for (int j = 0; j <= tt; j++) { e[j] = expf(attlg[tt][j] - m); s += e[j]; }
        float inv = 1.0f / s;
        for (int j = 0; j < 4; j++)
            g_eatt[tt][j][b] = (j <= tt) ? e[j] * inv : 0.0f;
    }
}

// ------ relation weights, UNNORMALIZED: w = exp(tau * (h·linW_r + b_r)) -----
// smem-staged: block = (t, 8 r's). hT[t] (16KB) + 8 lin_W rows (4KB) staged
// once; each warp computes one r entirely from shared memory. (R11 form.)
__global__ void k_wexp(const float* __restrict__ lin_W, const float* __restrict__ lin_b) {
    __shared__ float hs[Hd * Bsz];   // [d][b], 16 KB
    __shared__ float ws[8][Hd];      // 8 weight rows, 4 KB
    __shared__ float wb[8];
    int t = blockIdx.x / 50;
    int rbase = (blockIdx.x % 50) * 8;
    int tid = threadIdx.x;  // 256
    {
        const float4* src = reinterpret_cast<const float4*>(g_rnnT[t]);
        float4* dst = reinterpret_cast<float4*>(hs);
#pragma unroll
        for (int i = 0; i < 4; i++) dst[tid + 256 * i] = src[tid + 256 * i];
        const float4* wsrc = reinterpret_cast<const float4*>(lin_W + rbase * Hd);
        reinterpret_cast<float4*>(ws)[tid] = wsrc[tid];
        if (tid < 8) wb[tid] = lin_b[rbase + tid];
    }
    __syncthreads();
    int w = tid >> 5, lane = tid & 31;
    const float* wr = ws[w];
    float a0 = 0.0f, a1 = 0.0f, a2 = 0.0f, a3 = 0.0f;
#pragma unroll
    for (int d = 0; d < Hd; d += 4) {
        a0 += wr[d + 0] * hs[(d + 0) * Bsz + lane];
        a1 += wr[d + 1] * hs[(d + 1) * Bsz + lane];
        a2 += wr[d + 2] * hs[(d + 2) * Bsz + lane];
        a3 += wr[d + 3] * hs[(d + 3) * Bsz + lane];
    }
    float l = ((a0 + a1) + (a2 + a3) + wb[w]) * TAU1;
    g_wT[t][(rbase + w) * Bsz + lane] = expf(l);
}

// norm for state j (j>=1) = 1/max(g_sums[j-1][b], 1e-7); state 0 norm = 1
__device__ __forceinline__ float4 attn_vec(int t, int j, int q) {
    float4 e = reinterpret_cast<const float4*>(g_eatt)[(t * 4 + j) * 8 + q];
    if (j >= 1) {
        float4 s = reinterpret_cast<const float4*>(g_sums)[(j - 1) * 8 + q];
        e.x *= 1.0f / fmaxf(s.x, 1e-7f);
        e.y *= 1.0f / fmaxf(s.y, 1e-7f);
        e.z *= 1.0f / fmaxf(s.z, 1e-7f);
        e.w *= 1.0f / fmaxf(s.w, 1e-7f);
    }
    return e;
}

// ------- combine states -> g_inp + nz flags + zero next state (t=1,2) ------
__global__ void k_inp(const int* __restrict__ input_x, int t) {
    int tid0 = blockIdx.x * blockDim.x + threadIdx.x;   // 320*256 = 81920
    int q = tid0 & 7;                                    // stride 81920 % 8 == 0
    float4 a0 = attn_vec(t, 0, q);
    float4 a1 = attn_vec(t, 1, q);
    float4 a2 = (t >= 2) ? attn_vec(t, 2, q) : make_float4(0, 0, 0, 0);
    int4 xi = reinterpret_cast<const int4*>(input_x)[q];
    const float4* __restrict__ s1 = reinterpret_cast<const float4*>(g_states[1]);
    const float4* __restrict__ s2 = reinterpret_cast<const float4*>(g_states[2]);
    float4* inp4 = reinterpret_cast<float4*>(g_inp);
    float4* snew = reinterpret_cast<float4*>(g_states[t + 1]);
    const float4 z = make_float4(0.0f, 0.0f, 0.0f, 0.0f);
    int lane = threadIdx.x & 31;
    for (int u = tid0; u < Ecnt * 8; u += 81920) {
        int e = u >> 3;
        float4 v = make_float4(xi.x == e ? a0.x : 0.0f, xi.y == e ? a0.y : 0.0f,
                               xi.z == e ? a0.z : 0.0f, xi.w == e ? a0.w : 0.0f);
        {
            float4 s = s1[u];
            v.x += a1.x * s.x; v.y += a1.y * s.y; v.z += a1.z * s.z; v.w += a1.w * s.w;
        }
        if (t >= 2) {
            float4 s = s2[u];
            v.x += a2.x * s.x; v.y += a2.y * s.y; v.z += a2.z * s.z; v.w += a2.w * s.w;
        }
        inp4[u] = v;
        snew[u] = z;
        bool nzv = (v.x != 0.0f) | (v.y != 0.0f) | (v.z != 0.0f) | (v.w != 0.0f);
        unsigned m = __ballot_sync(0xffffffffu, nzv);
        if ((lane & 7) == 0) g_nz[e] = ((m >> ((lane >> 3) * 8)) & 0xffu) ? 1 : 0;
    }
}

// -------- propagate: sparse-aware, packed indices, fused batch sums --------
__global__ void k_prop(const int* __restrict__ rels, int t, int nE) {
    const float4* __restrict__ x4 = reinterpret_cast<const float4*>(g_inp);
    float4* s4 = reinterpret_cast<float4*>(g_states[t + 1]);
    const float4* __restrict__ w4 = reinterpret_cast<const float4*>(g_wT[t]);
    int lane = threadIdx.x & 31;
    int q = lane & 7;
    int sub = lane >> 3;
    int warpId = (blockIdx.x * blockDim.x + threadIdx.x) >> 5;
    int nWarp = (gridDim.x * blockDim.x) >> 5;
    float4 acc = make_float4(0.0f, 0.0f, 0.0f, 0.0f);
    for (int e = warpId * 4 + sub; e < nE; e += nWarp * 4) {
        unsigned ht = g_ht[e];
        int h = ht >> 16, tl = ht & 0xffff;
        bool fh = g_nz[h] != 0, ft = g_nz[tl] != 0;
        if (fh | ft) {
            int r = rels[e];
            if (fh) {
                float4 xh = x4[h * 8 + q];
                if (xh.x != 0.0f || xh.y != 0.0f || xh.z != 0.0f || xh.w != 0.0f) {
                    float4 w1 = w4[r * 8 + q];
                    float4 m1 = make_float4(xh.x * w1.x, xh.y * w1.y,
                                            xh.z * w1.z, xh.w * w1.w);
                    red_add_v4(&s4[tl * 8 + q], m1);
                    acc.x += m1.x; acc.y += m1.y; acc.z += m1.z; acc.w += m1.w;
                }
            }
            if (ft) {
                float4 xt = x4[tl * 8 + q];
                if (xt.x != 0.0f || xt.y != 0.0f || xt.z != 0.0f || xt.w != 0.0f) {
                    float4 w2 = w4[(r + RSIZEc) * 8 + q];
                    float4 m2 = make_float4(xt.x * w2.x, xt.y * w2.y,
                                            xt.z * w2.z, xt.w * w2.w);
                    red_add_v4(&s4[h * 8 + q], m2);
                    acc.x += m2.x; acc.y += m2.y; acc.z += m2.z; acc.w += m2.w;
                }
            }
        }
    }
    acc.x += __shfl_xor_sync(0xffffffffu, acc.x, 8);
    acc.y += __shfl_xor_sync(0xffffffffu, acc.y, 8);
    acc.z += __shfl_xor_sync(0xffffffffu, acc.z, 8);
    acc.w += __shfl_xor_sync(0xffffffffu, acc.w, 8);
    acc.x += __shfl_xor_sync(0xffffffffu, acc.x, 16);
    acc.y += __shfl_xor_sync(0xffffffffu, acc.y, 16);
    acc.z += __shfl_xor_sync(0xffffffffu, acc.z, 16);
    acc.w += __shfl_xor_sync(0xffffffffu, acc.w, 16);
    __shared__ float sblk[Bsz];
    if (threadIdx.x < Bsz) sblk[threadIdx.x] = 0.0f;
    __syncthreads();
    if (lane < 8) {
        atomicAdd(&sblk[q * 4 + 0], acc.x);
        atomicAdd(&sblk[q * 4 + 1], acc.y);
        atomicAdd(&sblk[q * 4 + 2], acc.z);
        atomicAdd(&sblk[q * 4 + 3], acc.w);
    }
    __syncthreads();
    if (threadIdx.x < Bsz) atomicAdd(&g_sums[t][threadIdx.x], sblk[threadIdx.x]);
}

// ------- final combine, tiled transpose to (B, E); 2 tiles per block -------
__global__ void k_final(const int* __restrict__ input_x, float* __restrict__ out) {
    __shared__ float tile[32][33];
    int r = threadIdx.x >> 3, q = threadIdx.x & 7;
    float4 a0 = attn_vec(3, 0, q);
    float4 a1 = attn_vec(3, 1, q);
    float4 a2 = attn_vec(3, 2, q);
    float4 a3 = attn_vec(3, 3, q);
    int4 xi = reinterpret_cast<const int4*>(input_x)[q];
    const float4* __restrict__ s1 = reinterpret_cast<const float4*>(g_states[1]);
    const float4* __restrict__ s2 = reinterpret_cast<const float4*>(g_states[2]);
    const float4* __restrict__ s3 = reinterpret_cast<const float4*>(g_states[3]);
    int w = threadIdx.x >> 5, lane = threadIdx.x & 31;
#pragma unroll
    for (int tt = 0; tt < 2; tt++) {
        int e0 = blockIdx.x * 64 + tt * 32;
        int e = e0 + r;
        int u = e * 8 + q;
        float4 v1 = s1[u], v2 = s2[u], v3 = s3[u];
        float4 v;
        v.x = (xi.x == e ? a0.x : 0.0f) + a1.x * v1.x + a2.x * v2.x + a3.x * v3.x;
        v.y = (xi.y == e ? a0.y : 0.0f) + a1.y * v1.y + a2.y * v2.y + a3.y * v3.y;
        v.z = (xi.z == e ? a0.z : 0.0f) + a1.z * v1.z + a2.z * v2.z + a3.z * v3.z;
        v.w = (xi.w == e ? a0.w : 0.0f) + a1.w * v1.w + a2.w * v2.w + a3.w * v3.w;
        tile[r][4 * q + 0] = v.x;
        tile[r][4 * q + 1] = v.y;
        tile[r][4 * q + 2] = v.z;
        tile[r][4 * q + 3] = v.w;
        __syncthreads();
#pragma unroll
        for (int bb = 0; bb < 4; bb++) {
            int b = w * 4 + bb;
            out[b * Ecnt + e0 + lane] = tile[lane][b];
        }
        __syncthreads();
    }
}

// ---------------- launch ----------------------------------------------------
extern "C" void kernel_launch(void* const* d_in, const int* in_sizes, int n_in,
                              void* d_out, int out_size) {
    const int* input_x = (const int*)d_in[0];
    const int* input_r = (const int*)d_in[1];
    const int* heads   = (const int*)d_in[2];
    const int* tails   = (const int*)d_in[3];
    const int* rels    = (const int*)d_in[4];
    const float* emb_W = (const float*)d_in[5];
    const float* W_ih  = (const float*)d_in[6];
    const float* W_hh  = (const float*)d_in[7];
    const float* b_ih  = (const float*)d_in[8];
    const float* b_hh  = (const float*)d_in[9];
    const float* lin_W = (const float*)d_in[10];
    const float* lin_b = (const float*)d_in[11];
    int nE = in_sizes[2];
    float* out = (float*)d_out;

    k_prep<<<449, 256>>>(W_ih, W_hh, input_x, heads, tails, nE);
    k_lstm4<<<32, 1024>>>(emb_W, input_r, b_ih, b_hh);
    k_wexp<<<150, 256>>>(lin_W, lin_b);
    k_prop<<<1184, 256>>>(rels, 0, nE);
    for (int t = 1; t < 3; t++) {
        k_inp<<<320, 256>>>(input_x, t);
        k_prop<<<1184, 256>>>(rels, t, nE);
    }
    k_final<<<625, 256>>>(input_x, out);
}

// round 16
// speedup vs baseline: 1.1596x; 1.0489x over previous
#include <cuda_runtime.h>
#include <math.h>

#define Ecnt 40000
#define Bsz 32
#define Hd 128
#define NRELc 400
#define RSIZEc 200
#define TAU1 10.0f
#define NEMAX 1000000

// ---------------- scratch (static device memory; no allocs) ----------------
// state 0 is virtual (one-hot from input_x); states 1..3 are materialized.
__device__ float g_states[4][Ecnt * Bsz];   // [t][e*32+b]; index 0 unused
__device__ float g_inp[Ecnt * Bsz];         // att-combined input to propagate
__device__ unsigned char g_nz[Ecnt];        // per-entity nonzero flag for g_inp
__device__ unsigned g_ht[NEMAX];            // packed (head<<16)|tail per edge
__device__ float g_rnnT[4][Hd * Bsz];       // LSTM hidden, transposed [t][d*32+b]
__device__ float g_eatt[4][4][Bsz];         // softmaxed attention [t][tp][b]
__device__ float g_WihT[Hd * 4 * Hd];       // [d][k]
__device__ float g_WhhT[Hd * 4 * Hd];       // [d][k]
__device__ float g_wT[3][NRELc * Bsz];      // UNNORMALIZED exp weights [t][r*32+b]
__device__ float g_sums[3][Bsz];            // per-prop-step message sums

__device__ __forceinline__ float sigf(float x) { return 1.0f / (1.0f + expf(-x)); }

__device__ __forceinline__ void red_add_v4(float4* p, float4 v) {
    asm volatile("red.global.add.v4.f32 [%0], {%1, %2, %3, %4};"
                 :: "l"(p), "f"(v.x), "f"(v.y), "f"(v.z), "f"(v.w)
                 : "memory");
}

// ===== prep: transposes (0..127) + seed (128) + edge pack (129..288) =======
// ===== + state/sums zeroing (289..448)                                 =====
__global__ void k_prep(const float* __restrict__ W_ih,
                       const float* __restrict__ W_hh,
                       const int* __restrict__ input_x,
                       const int* __restrict__ heads,
                       const int* __restrict__ tails, int nE) {
    int bx = blockIdx.x;
    if (bx < 128) {
        __shared__ float tile[32][33];
        int m = bx >> 6;           // 0: ih, 1: hh
        int bid = bx & 63;
        int kb = (bid >> 2) * 32;
        int db = (bid & 3) * 32;
        const float* __restrict__ W = m ? W_hh : W_ih;
        float* WT = m ? g_WhhT : g_WihT;
        int tx = threadIdx.x & 31, ty0 = threadIdx.x >> 5;   // 32x8
#pragma unroll
        for (int i = 0; i < 4; i++) {
            int ty = ty0 + 8 * i;
            tile[ty][tx] = W[(kb + ty) * Hd + db + tx];
        }
        __syncthreads();
#pragma unroll
        for (int i = 0; i < 4; i++) {
            int ty = ty0 + 8 * i;
            WT[(db + ty) * (4 * Hd) + kb + tx] = tile[tx][ty];
        }
    } else if (bx == 128) {
        // seed: zero nz flags, zero 32 one-hot lines, set one-hot entries
        int i = threadIdx.x;  // 256
        int4* nz4 = reinterpret_cast<int4*>(g_nz);
        for (int j = i; j < Ecnt / 16; j += 256) nz4[j] = make_int4(0, 0, 0, 0);
        __syncthreads();
        int e = input_x[i >> 3];
        reinterpret_cast<float4*>(g_inp)[e * 8 + (i & 7)] =
            make_float4(0.0f, 0.0f, 0.0f, 0.0f);
        __syncthreads();
        if (i < Bsz) {
            int e2 = input_x[i];
            g_inp[e2 * Bsz + i] = 1.0f;
            g_nz[e2] = 1;
        }
    } else if (bx < 289) {
        // pack edges: h,t < 40000 < 2^16
        int i = (bx - 129) * 256 + threadIdx.x;  // 40960 threads
        for (int e = i; e < nE; e += 160 * 256)
            g_ht[e] = ((unsigned)heads[e] << 16) | (unsigned)tails[e];
    } else {
        // zero state[1] + sums
        int i = (bx - 289) * 256 + threadIdx.x;  // 40960 threads
        const float4 z = make_float4(0.0f, 0.0f, 0.0f, 0.0f);
        float4* s4 = reinterpret_cast<float4*>(g_states[1]);
        for (int j = i; j < Ecnt * 8; j += 160 * 256) s4[j] = z;
        if (i < 3 * Bsz) ((float*)g_sums)[i] = 0.0f;
    }
}

// ------- LSTM: ih-pre + 4 steps + attention, d-split x2, 1024 thr ----------
__global__ void __launch_bounds__(1024, 1)
k_lstm4(const float* __restrict__ emb_W, const int* __restrict__ input_r,
        const float* __restrict__ b_ih, const float* __restrict__ b_hh) {
    __shared__ float xs0[Hd];
    __shared__ float xs1[Hd];
    __shared__ float cs[Hd];
    __shared__ float hist[4][Hd];
    __shared__ float gp[2][4 * Hd];
    __shared__ float attlg[4][4];
    int b = blockIdx.x, tid = threadIdx.x;
    int k = tid & 511, half = tid >> 9;
    int d0 = half * 64;
    if (tid < Hd) {
        xs0[tid] = emb_W[input_r[b] * Hd + tid];
        cs[tid] = 0.0f;
    } else if (tid < 2 * Hd) {
        xs1[tid - Hd] = emb_W[NRELc * Hd + (tid - Hd)];
    }
    __syncthreads();
    float bias = half ? 0.0f : (b_ih[k] + b_hh[k]);
    float p0a = bias, p0b = 0.0f, p1a = bias, p1b = 0.0f;
#pragma unroll
    for (int i = 0; i < 64; i += 2) {
        int d = d0 + i;
        float wa = g_WihT[d * (4 * Hd) + k];
        float wb = g_WihT[(d + 1) * (4 * Hd) + k];
        p0a += xs0[d] * wa;     p0b += xs0[d + 1] * wb;
        p1a += xs1[d] * wa;     p1b += xs1[d + 1] * wb;
    }
    float pre0 = p0a + p0b, pre1 = p1a + p1b;
    // ---- t = 0: h = 0, gates = pre0 directly
    gp[half][k] = pre0;
    __syncthreads();
    if (tid < Hd) {
        float ig = gp[0][tid] + gp[1][tid];
        float gg = gp[0][2 * Hd + tid] + gp[1][2 * Hd + tid];
        float og = gp[0][3 * Hd + tid] + gp[1][3 * Hd + tid];
        float c = sigf(ig) * tanhf(gg);   // c_prev = 0: forget term vanishes
        float h = sigf(og) * tanhf(c);
        cs[tid] = c;
        hist[0][tid] = h;
        g_rnnT[0][tid * Bsz + b] = h;
    }
    __syncthreads();
    // ---- t = 1..3: full unroll, 4 accumulators for MLP
#pragma unroll
    for (int t = 1; t < 4; t++) {
        float aa = (t < 3) ? pre0 : pre1, ab = 0.0f, ac = 0.0f, ad = 0.0f;
        const float* hprev = hist[t - 1];
#pragma unroll
        for (int i = 0; i < 64; i += 4) {
            int d = d0 + i;
            aa += hprev[d] * g_WhhT[d * (4 * Hd) + k];
            ab += hprev[d + 1] * g_WhhT[(d + 1) * (4 * Hd) + k];
            ac += hprev[d + 2] * g_WhhT[(d + 2) * (4 * Hd) + k];
            ad += hprev[d + 3] * g_WhhT[(d + 3) * (4 * Hd) + k];
        }
        gp[half][k] = (aa + ab) + (ac + ad);
        __syncthreads();
        if (tid < Hd) {
            float ig = gp[0][tid] + gp[1][tid];
            float fg = gp[0][Hd + tid] + gp[1][Hd + tid];
            float gg = gp[0][2 * Hd + tid] + gp[1][2 * Hd + tid];
            float og = gp[0][3 * Hd + tid] + gp[1][3 * Hd + tid];
            float c = sigf(fg) * cs[tid] + sigf(ig) * tanhf(gg);
            float h = sigf(og) * tanhf(c);
            cs[tid] = c;
            hist[t][tid] = h;
            g_rnnT[t][tid * Bsz + b] = h;
        }
        __syncthreads();
    }
    // attention logits: warps 0..15 = (t,tp)
    int w = tid >> 5, lane = tid & 31;
    if (w < 16) {
        int t = w >> 2, tp = w & 3;
        if (tp <= t) {
            float acc = 0.0f;
#pragma unroll
            for (int i = 0; i < 4; i++) {
                int d = lane + 32 * i;
                acc += hist[t][d] * hist[tp][d];
            }
#pragma unroll
            for (int s = 16; s > 0; s >>= 1) acc += __shfl_xor_sync(0xffffffffu, acc, s);
            if (lane == 0) attlg[t][tp] = acc;
        }
    }
    __syncthreads();
    if (tid < 4) {
        int tt = tid;
        float m = -1e30f;
        for (int j = 0; j <= tt; j++) m = fmaxf(m, attlg[tt][j]);
        float s = 0.0f, e[4];
        for (int j = 0; j <= tt; j++) { e[j] = expf(attlg[tt][j] - m); s += e[j]; }
        float inv = 1.0f / s;
        for (int j = 0; j < 4; j++)
            g_eatt[tt][j][b] = (j <= tt) ? e[j] * inv : 0.0f;
    }
}

// ------ relation weights, UNNORMALIZED: w = exp(tau * (h·linW_r + b_r)) -----
__global__ void k_wexp(const float* __restrict__ lin_W, const float* __restrict__ lin_b) {
    __shared__ float hs[Hd * Bsz];   // [d][b], 16 KB
    __shared__ float ws[8][Hd];      // 8 weight rows, 4 KB
    __shared__ float wb[8];
    int t = blockIdx.x / 50;
    int rbase = (blockIdx.x % 50) * 8;
    int tid = threadIdx.x;  // 256
    {
        const float4* src = reinterpret_cast<const float4*>(g_rnnT[t]);
        float4* dst = reinterpret_cast<float4*>(hs);
#pragma unroll
        for (int i = 0; i < 4; i++) dst[tid + 256 * i] = src[tid + 256 * i];
        const float4* wsrc = reinterpret_cast<const float4*>(lin_W + rbase * Hd);
        reinterpret_cast<float4*>(ws)[tid] = wsrc[tid];
        if (tid < 8) wb[tid] = lin_b[rbase + tid];
    }
    __syncthreads();
    int w = tid >> 5, lane = tid & 31;
    const float* wr = ws[w];
    float a0 = 0.0f, a1 = 0.0f, a2 = 0.0f, a3 = 0.0f;
#pragma unroll
    for (int d = 0; d < Hd; d += 4) {
        a0 += wr[d + 0] * hs[(d + 0) * Bsz + lane];
        a1 += wr[d + 1] * hs[(d + 1) * Bsz + lane];
        a2 += wr[d + 2] * hs[(d + 2) * Bsz + lane];
        a3 += wr[d + 3] * hs[(d + 3) * Bsz + lane];
    }
    float l = ((a0 + a1) + (a2 + a3) + wb[w]) * TAU1;
    g_wT[t][(rbase + w) * Bsz + lane] = expf(l);
}

// norm for state j (j>=1) = 1/max(g_sums[j-1][b], 1e-7); state 0 norm = 1
__device__ __forceinline__ float4 attn_vec(int t, int j, int q) {
    float4 e = reinterpret_cast<const float4*>(g_eatt)[(t * 4 + j) * 8 + q];
    if (j >= 1) {
        float4 s = reinterpret_cast<const float4*>(g_sums)[(j - 1) * 8 + q];
        e.x *= 1.0f / fmaxf(s.x, 1e-7f);
        e.y *= 1.0f / fmaxf(s.y, 1e-7f);
        e.z *= 1.0f / fmaxf(s.z, 1e-7f);
        e.w *= 1.0f / fmaxf(s.w, 1e-7f);
    }
    return e;
}

// ------- combine states -> g_inp + nz flags + zero next state (t=1,2) ------
__global__ void k_inp(const int* __restrict__ input_x, int t) {
    int tid0 = blockIdx.x * blockDim.x + threadIdx.x;   // 320*256 = 81920
    int q = tid0 & 7;                                    // stride 81920 % 8 == 0
    float4 a0 = attn_vec(t, 0, q);
    float4 a1 = attn_vec(t, 1, q);
    float4 a2 = (t >= 2) ? attn_vec(t, 2, q) : make_float4(0, 0, 0, 0);
    int4 xi = reinterpret_cast<const int4*>(input_x)[q];
    const float4* __restrict__ s1 = reinterpret_cast<const float4*>(g_states[1]);
    const float4* __restrict__ s2 = reinterpret_cast<const float4*>(g_states[2]);
    float4* inp4 = reinterpret_cast<float4*>(g_inp);
    float4* snew = reinterpret_cast<float4*>(g_states[t + 1]);
    const float4 z = make_float4(0.0f, 0.0f, 0.0f, 0.0f);
    int lane = threadIdx.x & 31;
    for (int u = tid0; u < Ecnt * 8; u += 81920) {
        int e = u >> 3;
        float4 v = make_float4(xi.x == e ? a0.x : 0.0f, xi.y == e ? a0.y : 0.0f,
                               xi.z == e ? a0.z : 0.0f, xi.w == e ? a0.w : 0.0f);
        {
            float4 s = s1[u];
            v.x += a1.x * s.x; v.y += a1.y * s.y; v.z += a1.z * s.z; v.w += a1.w * s.w;
        }
        if (t >= 2) {
            float4 s = s2[u];
            v.x += a2.x * s.x; v.y += a2.y * s.y; v.z += a2.z * s.z; v.w += a2.w * s.w;
        }
        inp4[u] = v;
        snew[u] = z;
        bool nzv = (v.x != 0.0f) | (v.y != 0.0f) | (v.z != 0.0f) | (v.w != 0.0f);
        unsigned m = __ballot_sync(0xffffffffu, nzv);
        if ((lane & 7) == 0) g_nz[e] = ((m >> ((lane >> 3) * 8)) & 0xffu) ? 1 : 0;
    }
}

// ------- shared edge-processing core (8 lanes per edge, lane q) -------------
__device__ __forceinline__ void prop_edge(
    int h, int tl, int r, bool fh, bool ft, int q,
    const float4* __restrict__ x4, float4* s4, const float4* __restrict__ w4,
    float4& acc) {
    if (fh) {
        float4 xh = x4[h * 8 + q];
        if (xh.x != 0.0f || xh.y != 0.0f || xh.z != 0.0f || xh.w != 0.0f) {
            float4 w1 = w4[r * 8 + q];
            float4 m1 = make_float4(xh.x * w1.x, xh.y * w1.y, xh.z * w1.z, xh.w * w1.w);
            red_add_v4(&s4[tl * 8 + q], m1);
            acc.x += m1.x; acc.y += m1.y; acc.z += m1.z; acc.w += m1.w;
        }
    }
    if (ft) {
        float4 xt = x4[tl * 8 + q];
        if (xt.x != 0.0f || xt.y != 0.0f || xt.z != 0.0f || xt.w != 0.0f) {
            float4 w2 = w4[(r + RSIZEc) * 8 + q];
            float4 m2 = make_float4(xt.x * w2.x, xt.y * w2.y, xt.z * w2.z, xt.w * w2.w);
            red_add_v4(&s4[h * 8 + q], m2);
            acc.x += m2.x; acc.y += m2.y; acc.z += m2.z; acc.w += m2.w;
        }
    }
}

__device__ __forceinline__ void prop_epilogue(float4 acc, int lane, int q, int t) {
    acc.x += __shfl_xor_sync(0xffffffffu, acc.x, 8);
    acc.y += __shfl_xor_sync(0xffffffffu, acc.y, 8);
    acc.z += __shfl_xor_sync(0xffffffffu, acc.z, 8);
    acc.w += __shfl_xor_sync(0xffffffffu, acc.w, 8);
    acc.x += __shfl_xor_sync(0xffffffffu, acc.x, 16);
    acc.y += __shfl_xor_sync(0xffffffffu, acc.y, 16);
    acc.z += __shfl_xor_sync(0xffffffffu, acc.z, 16);
    acc.w += __shfl_xor_sync(0xffffffffu, acc.w, 16);
    __shared__ float sblk[Bsz];
    if (threadIdx.x < Bsz) sblk[threadIdx.x] = 0.0f;
    __syncthreads();
    if (lane < 8) {
        atomicAdd(&sblk[q * 4 + 0], acc.x);
        atomicAdd(&sblk[q * 4 + 1], acc.y);
        atomicAdd(&sblk[q * 4 + 2], acc.z);
        atomicAdd(&sblk[q * 4 + 3], acc.w);
    }
    __syncthreads();
    if (threadIdx.x < Bsz) atomicAdd(&g_sums[t][threadIdx.x], sblk[threadIdx.x]);
}

// ---- sparse propagate (t=0,1): per-lane scan + ballot-compacted process ----
// All shuffles are executed by ALL 32 lanes (uniform control flow); only the
// guarded loads/REDs diverge. Fixes the R15 divergent-shfl IMA.
__global__ void k_props(const int* __restrict__ rels, int t, int nE) {
    const float4* __restrict__ x4 = reinterpret_cast<const float4*>(g_inp);
    float4* s4 = reinterpret_cast<float4*>(g_states[t + 1]);
    const float4* __restrict__ w4 = reinterpret_cast<const float4*>(g_wT[t]);
    int lane = threadIdx.x & 31;
    int q = lane & 7;
    int sub = lane >> 3;
    int warpId = (blockIdx.x * blockDim.x + threadIdx.x) >> 5;
    int nWarp = (gridDim.x * blockDim.x) >> 5;
    float4 acc = make_float4(0.0f, 0.0f, 0.0f, 0.0f);
    for (int base = warpId * 32; base < nE; base += nWarp * 32) {
        int e = base + lane;
        unsigned ht = 0;
        bool fh = false, ft = false;
        if (e < nE) {
            ht = g_ht[e];
            fh = g_nz[ht >> 16] != 0;
            ft = g_nz[ht & 0xffffu] != 0;
        }
        unsigned mact = __ballot_sync(0xffffffffu, fh | ft);
        int fhv = fh ? 1 : 0, ftv = ft ? 1 : 0;
        while (mact) {
            // subgroup `sub` takes the sub-th set bit
            unsigned mm = mact;
            if (sub > 0) mm &= mm - 1;
            if (sub > 1) mm &= mm - 1;
            if (sub > 2) mm &= mm - 1;
            int myb = __ffs(mm) - 1;      // -1 if fewer than sub+1 bits remain
            int src = myb < 0 ? 0 : myb;  // clamp: shuffles run on ALL lanes
            unsigned ht2 = __shfl_sync(0xffffffffu, ht, src);
            int fh2 = __shfl_sync(0xffffffffu, fhv, src);
            int ft2 = __shfl_sync(0xffffffffu, ftv, src);
            if (myb >= 0) {
                int r2 = rels[base + myb];   // broadcast within subgroup
                prop_edge((int)(ht2 >> 16), (int)(ht2 & 0xffffu), r2,
                          fh2 != 0, ft2 != 0, q, x4, s4, w4, acc);
            }
            // consume the 4 lowest set bits (warp-uniform)
            mact &= mact - 1;
            if (mact) mact &= mact - 1;
            if (mact) mact &= mact - 1;
            if (mact) mact &= mact - 1;
        }
    }
    prop_epilogue(acc, lane, q, t);
}

// -------- dense propagate (t=2): subgroup-per-edge (original form) ---------
__global__ void k_prop(const int* __restrict__ rels, int t, int nE) {
    const float4* __restrict__ x4 = reinterpret_cast<const float4*>(g_inp);
    float4* s4 = reinterpret_cast<float4*>(g_states[t + 1]);
    const float4* __restrict__ w4 = reinterpret_cast<const float4*>(g_wT[t]);
    int lane = threadIdx.x & 31;
    int q = lane & 7;
    int sub = lane >> 3;
    int warpId = (blockIdx.x * blockDim.x + threadIdx.x) >> 5;
    int nWarp = (gridDim.x * blockDim.x) >> 5;
    float4 acc = make_float4(0.0f, 0.0f, 0.0f, 0.0f);
    for (int e = warpId * 4 + sub; e < nE; e += nWarp * 4) {
        unsigned ht = g_ht[e];
        int h = ht >> 16, tl = ht & 0xffff;
        bool fh = g_nz[h] != 0, ft = g_nz[tl] != 0;
        if (fh | ft) {
            int r = rels[e];
            prop_edge(h, tl, r, fh, ft, q, x4, s4, w4, acc);
        }
    }
    prop_epilogue(acc, lane, q, t);
}

// ------- final combine, tiled transpose to (B, E); 2 tiles per block -------
__global__ void k_final(const int* __restrict__ input_x, float* __restrict__ out) {
    __shared__ float tile[32][33];
    int r = threadIdx.x >> 3, q = threadIdx.x & 7;
    float4 a0 = attn_vec(3, 0, q);
    float4 a1 = attn_vec(3, 1, q);
    float4 a2 = attn_vec(3, 2, q);
    float4 a3 = attn_vec(3, 3, q);
    int4 xi = reinterpret_cast<const int4*>(input_x)[q];
    const float4* __restrict__ s1 = reinterpret_cast<const float4*>(g_states[1]);
    const float4* __restrict__ s2 = reinterpret_cast<const float4*>(g_states[2]);
    const float4* __restrict__ s3 = reinterpret_cast<const float4*>(g_states[3]);
    int w = threadIdx.x >> 5, lane = threadIdx.x & 31;
#pragma unroll
    for (int tt = 0; tt < 2; tt++) {
        int e0 = blockIdx.x * 64 + tt * 32;
        int e = e0 + r;
        int u = e * 8 + q;
        float4 v1 = s1[u], v2 = s2[u], v3 = s3[u];
        float4 v;
        v.x = (xi.x == e ? a0.x : 0.0f) + a1.x * v1.x + a2.x * v2.x + a3.x * v3.x;
        v.y = (xi.y == e ? a0.y : 0.0f) + a1.y * v1.y + a2.y * v2.y + a3.y * v3.y;
        v.z = (xi.z == e ? a0.z : 0.0f) + a1.z * v1.z + a2.z * v2.z + a3.z * v3.z;
        v.w = (xi.w == e ? a0.w : 0.0f) + a1.w * v1.w + a2.w * v2.w + a3.w * v3.w;
        tile[r][4 * q + 0] = v.x;
        tile[r][4 * q + 1] = v.y;
        tile[r][4 * q + 2] = v.z;
        tile[r][4 * q + 3] = v.w;
        __syncthreads();
#pragma unroll
        for (int bb = 0; bb < 4; bb++) {
            int b = w * 4 + bb;
            out[b * Ecnt + e0 + lane] = tile[lane][b];
        }
        __syncthreads();
    }
}

// ---------------- launch ----------------------------------------------------
extern "C" void kernel_launch(void* const* d_in, const int* in_sizes, int n_in,
                              void* d_out, int out_size) {
    const int* input_x = (const int*)d_in[0];
    const int* input_r = (const int*)d_in[1];
    const int* heads   = (const int*)d_in[2];
    const int* tails   = (const int*)d_in[3];
    const int* rels    = (const int*)d_in[4];
    const float* emb_W = (const float*)d_in[5];
    const float* W_ih  = (const float*)d_in[6];
    const float* W_hh  = (const float*)d_in[7];
    const float* b_ih  = (const float*)d_in[8];
    const float* b_hh  = (const float*)d_in[9];
    const float* lin_W = (const float*)d_in[10];
    const float* lin_b = (const float*)d_in[11];
    int nE = in_sizes[2];
    float* out = (float*)d_out;

    k_prep<<<449, 256>>>(W_ih, W_hh, input_x, heads, tails, nE);
    k_lstm4<<<32, 1024>>>(emb_W, input_r, b_ih, b_hh);
    k_wexp<<<150, 256>>>(lin_W, lin_b);
    k_props<<<1184, 256>>>(rels, 0, nE);
    k_inp<<<320, 256>>>(input_x, 1);
    k_props<<<1184, 256>>>(rels, 1, nE);
    k_inp<<<320, 256>>>(input_x, 2);
    k_prop<<<1184, 256>>>(rels, 2, nE);
    k_final<<<625, 256>>>(input_x, out);
}